// round 9
// baseline (speedup 1.0000x reference)
#include <cuda_runtime.h>
#include <cuda_fp16.h>
#include <cstdint>

#define BATCH   64
#define CH      256
#define HH      32
#define WW      32
#define NCHUNK  16        // 16 ci-chunks of 16

#define THREADS 256
#define SP_ROWS 4         // M = 128 spatial (4 rows x 32 cols)
#define CO_TILE 128       // N

// X persistent region: [row 0..5][col 0..33][ci 0..255] fp16, slot = 512B data + 16B pad
#define X_SLOT    528
#define X_BYTES   (6 * 34 * X_SLOT)       // 107712
// W ring: [stage 2][tap 9][co 128][ci16] 48B slots
#define W_SLOT    48
#define W_STAGE   (9 * 128 * W_SLOT)      // 55296
#define SMEM_TOTAL (X_BYTES + 2 * W_STAGE) // 218304
#define OUT_STR   136                     // epilogue s_out stride (floats)

// Pre-transposed fp16 weights: [branch][ci_chunk 16][tap 9][co 256][ci16]
static __device__ __half g_wt[4u * 16 * 9 * 256 * 16];
// Pre-converted fp16 input: [b][h][w][ci]
static __device__ __half g_xh[(size_t)BATCH * HH * WW * CH];

static __device__ __forceinline__ uint32_t s2u(const void* p) {
    return (uint32_t)__cvta_generic_to_shared(p);
}

static __device__ __forceinline__ void cp16p(uint32_t dst, const void* src, int ok) {
    asm volatile(
        "{\n\t.reg .pred p;\n\t"
        "setp.ne.b32 p, %2, 0;\n\t"
        "@p  cp.async.cg.shared.global [%0], [%1], 16;\n\t"
        "@!p cp.async.cg.shared.global [%0], [%1], 16, 0;\n\t}"
        :: "r"(dst), "l"(src), "r"(ok) : "memory");
}
static __device__ __forceinline__ void cp16(uint32_t dst, const void* src) {
    asm volatile("cp.async.cg.shared.global [%0], [%1], 16;"
                 :: "r"(dst), "l"(src) : "memory");
}
#define CP_COMMIT() asm volatile("cp.async.commit_group;" ::: "memory")
#define CP_WAIT0()  asm volatile("cp.async.wait_group 0;" ::: "memory")

#define LDSM4(r0, r1, r2, r3, addr)                                         \
    asm volatile("ldmatrix.sync.aligned.m8n8.x4.shared.b16 "                \
                 "{%0,%1,%2,%3}, [%4];"                                     \
                 : "=r"(r0), "=r"(r1), "=r"(r2), "=r"(r3) : "r"(addr))

#define MMA16816(c, a0, a1, a2, a3, b0, b1)                                 \
    asm volatile("mma.sync.aligned.m16n8k16.row.col.f32.f16.f16.f32 "       \
                 "{%0,%1,%2,%3}, {%4,%5,%6,%7}, {%8,%9}, {%0,%1,%2,%3};"    \
                 : "+f"((c)[0]), "+f"((c)[1]), "+f"((c)[2]), "+f"((c)[3])   \
                 : "r"(a0), "r"(a1), "r"(a2), "r"(a3), "r"(b0), "r"(b1))

// ---------------------------------------------------------------------------
// W[a][co][ci][tap] fp32 -> g_wt[a][ci>>4][tap][co][ci&15] fp16
// ---------------------------------------------------------------------------
__global__ __launch_bounds__(256)
void wt_transpose_kernel(const float* __restrict__ Wt)
{
    const int tid = blockIdx.x * 256 + threadIdx.x;   // 262144 total
    const int a   = tid >> 16;
    const int co  = (tid >> 8) & 255;
    const int ci  = tid & 255;
    const float* src = Wt + ((size_t)(a * 256 + co) * 256 + ci) * 9;
    const int kc   = ci >> 4;
    const int ci16 = ci & 15;
#pragma unroll
    for (int tap = 0; tap < 9; ++tap) {
        g_wt[((((size_t)a * 16 + kc) * 9 + tap) * 256 + co) * 16 + ci16] =
            __float2half_rn(src[tap]);
    }
}

// ---------------------------------------------------------------------------
// x[b][ci][h][w] fp32 -> g_xh[b][h][w][ci] fp16 (smem tile transpose)
// ---------------------------------------------------------------------------
__global__ __launch_bounds__(256)
void x_transpose_kernel(const float* __restrict__ x)
{
    __shared__ float tile[256 * 33];
    const int bb = blockIdx.x, h = blockIdx.y, t = threadIdx.x;
    const int tw = t & 31, tc = t >> 5;
    const float* src = x + (size_t)bb * 256 * (HH * WW) + h * WW;
#pragma unroll
    for (int p = 0; p < 32; ++p) {
        const int ci = p * 8 + tc;
        tile[ci * 33 + tw] = src[(size_t)ci * (HH * WW) + tw];
    }
    __syncthreads();
    __half* dst = g_xh + (size_t)(bb * HH + h) * WW * 256;
#pragma unroll
    for (int w = 0; w < 32; ++w)
        dst[w * 256 + t] = __float2half_rn(tile[t * 33 + w]);
}

// ---------------------------------------------------------------------------
// Main kernel: persistent-X, W-streamed, tap-decomposed fp16 HMMA conv
// ---------------------------------------------------------------------------
__global__ __launch_bounds__(THREADS, 1)
void conv_mma_kernel(const int*   __restrict__ arc,
                     const float* __restrict__ bias,
                     float*       __restrict__ out)
{
    extern __shared__ __align__(16) char smem[];

    const int t    = threadIdx.x;
    const int lane = t & 31;
    const int wid  = t >> 5;          // 0..7
    const int mw   = wid >> 1;        // 0..3  (spatial row within tile)
    const int nw   = wid & 1;         // 0..1  (co half)

    const int bb  = blockIdx.z;
    const int co0 = blockIdx.y * CO_TILE;
    const int h0  = blockIdx.x * SP_ROWS;
    const int a   = arc[bb];

    const uint32_t smem_u = s2u(smem);

    float acc[2][8][4];
#pragma unroll
    for (int mt = 0; mt < 2; ++mt)
#pragma unroll
        for (int nt = 0; nt < 8; ++nt)
#pragma unroll
            for (int k = 0; k < 4; ++k)
                acc[mt][nt][k] = 0.0f;

    // ---- stage X ONCE: 6x34 slots x 256 ci, zero-filled halo ----
    {
        const __half* xb = g_xh + (size_t)bb * (HH * WW) * 256;
#pragma unroll 1
        for (int e = t; e < 204 * 16; e += THREADS) {
            const int slot = e >> 4;
            const int part = e & 15;            // 32B sub-chunk of the 512B slot
            const int row  = slot / 34;
            const int col  = slot - 34 * row;
            const int gr   = h0 + row - 1;
            const int gc   = col - 1;
            const int ok   = ((unsigned)gr < (unsigned)HH) && ((unsigned)gc < (unsigned)WW);
            // keep the source address in-bounds even when masked (offset 0)
            const size_t off = ok ? (size_t)(gr * WW + gc) * 256 : (size_t)0;
            const __half* src = xb + off + part * 16;
            const uint32_t dst = smem_u + (uint32_t)(slot * X_SLOT + part * 32);
            cp16p(dst,      src,     ok);
            cp16p(dst + 16, src + 8, ok);
        }
    }

    // ---- W staging setup ----
    const __half* wbase = g_wt + (size_t)a * (16 * 9 * 256 * 16);
    const uint32_t wRing = smem_u + X_BYTES;
    auto prefetchW = [&](int it) {
        const uint32_t st = wRing + (uint32_t)((it & 1) * W_STAGE);
        const __half* wc = wbase + (size_t)it * (9 * 256 * 16);
#pragma unroll 1
        for (int s = t; s < 1152; s += THREADS) {
            const int tap = s >> 7;
            const int co  = s & 127;
            const __half* src = wc + ((size_t)tap * 256 + co0 + co) * 16;
            const uint32_t dst = st + (uint32_t)(s * W_SLOT);
            cp16(dst,      src);
            cp16(dst + 16, src + 8);
        }
    };

    prefetchW(0);
    CP_COMMIT();          // group: X + W0

    // per-lane ldmatrix offsets
    const uint32_t laneA = (uint32_t)((lane & 15) * X_SLOT + (lane >> 4) * 16);
    const uint32_t laneB = (uint32_t)(((((lane >> 4) & 1) * 8 + (lane & 7)) + nw * 64) * W_SLOT
                                      + ((lane >> 3) & 1) * 16);

    for (int it = 0; it < NCHUNK; ++it) {
        CP_WAIT0();                        // W(it) (and X on it=0) landed
        __syncthreads();                   // visible to all warps
        if (it + 1 < NCHUNK) { prefetchW(it + 1); CP_COMMIT(); }

        const uint32_t sw = wRing + (uint32_t)((it & 1) * W_STAGE);
        const uint32_t ciOff = (uint32_t)(it * 32);   // 16 ci * 2B within X slot
#pragma unroll
        for (int tap = 0; tap < 9; ++tap) {
            const int dh = tap / 3;
            const int dw = tap - 3 * dh;
            const uint32_t aAddr = smem_u + (uint32_t)(((mw + dh) * 34 + dw) * X_SLOT)
                                   + ciOff + laneA;
            uint32_t a0, a1, a2, a3, a4, a5, a6, a7;
            LDSM4(a0, a1, a2, a3, aAddr);
            LDSM4(a4, a5, a6, a7, aAddr + 16 * X_SLOT);
            const uint32_t bAddr = sw + (uint32_t)(tap * (128 * W_SLOT)) + laneB;
#pragma unroll
            for (int p = 0; p < 4; ++p) {
                uint32_t b0, b1, b2, b3;
                LDSM4(b0, b1, b2, b3, bAddr + p * (16 * W_SLOT));
                MMA16816(acc[0][2 * p],     a0, a1, a2, a3, b0, b1);
                MMA16816(acc[0][2 * p + 1], a0, a1, a2, a3, b2, b3);
                MMA16816(acc[1][2 * p],     a4, a5, a6, a7, b0, b1);
                MMA16816(acc[1][2 * p + 1], a4, a5, a6, a7, b2, b3);
            }
        }
        __syncthreads();                   // all done with W(it) before overwrite
    }

    // ---- epilogue: acc -> SMEM transpose -> coalesced global stores ----
    float* s_out = reinterpret_cast<float*>(smem);
    {
        const int m0g = mw * 32 + (lane >> 2);
#pragma unroll
        for (int mt = 0; mt < 2; ++mt) {
            const int m0 = m0g + mt * 16;
#pragma unroll
            for (int nt = 0; nt < 8; ++nt) {
                const int co = nw * 64 + nt * 8 + (lane & 3) * 2;
                s_out[co * OUT_STR + m0]           = acc[mt][nt][0];
                s_out[(co + 1) * OUT_STR + m0]     = acc[mt][nt][1];
                s_out[co * OUT_STR + m0 + 8]       = acc[mt][nt][2];
                s_out[(co + 1) * OUT_STR + m0 + 8] = acc[mt][nt][3];
            }
        }
    }
    __syncthreads();
    {
        const int co = t >> 1;       // 0..127
        const int mq = t & 1;
        const float bi = bias[a * CH + co0 + co];
        float* og = out + ((size_t)(bb * CH + co0 + co) * HH + h0) * WW;
        const float* sr = &s_out[co * OUT_STR];
#pragma unroll
        for (int i = 0; i < 16; ++i) {
            const int m = mq * 4 + i * 8;
            float4 v = *reinterpret_cast<const float4*>(sr + m);
            v.x += bi; v.y += bi; v.z += bi; v.w += bi;
            *reinterpret_cast<float4*>(og + m) = v;
        }
    }
}

extern "C" void kernel_launch(void* const* d_in, const int* in_sizes, int n_in,
                              void* d_out, int out_size)
{
    const float* x    = (const float*)d_in[0];  // [64,256,32,32]
    const int*   arc  = (const int*)  d_in[1];  // [64]
    const float* Wt   = (const float*)d_in[2];  // [4,256,256,3,3]
    const float* bias = (const float*)d_in[3];  // [4,256]
    float* out = (float*)d_out;                 // [64,256,32,32]

    wt_transpose_kernel<<<1024, 256>>>(Wt);
    x_transpose_kernel<<<dim3(BATCH, HH), 256>>>(x);

    cudaFuncSetAttribute(conv_mma_kernel,
                         cudaFuncAttributeMaxDynamicSharedMemorySize, SMEM_TOTAL);
    dim3 grid(HH / SP_ROWS, CH / CO_TILE, BATCH);   // (8, 2, 64) = 1024 CTAs
    conv_mma_kernel<<<grid, THREADS, SMEM_TOTAL>>>(arc, bias, out);
}